// round 1
// baseline (speedup 1.0000x reference)
#include <cuda_runtime.h>

#define T_LEN 1024
#define BATCH 4
#define EMB   1024
#define NH    16
#define HD    64
#define BH    (BATCH*NH)   // 64
#define NREL  33           // 2L+1

// Scratch (static device arrays: allocation-free per harness rules)
__device__ float g_q[BH * T_LEN * HD];        // [bh][t][d], pre-scaled by 0.125
__device__ float g_k[BH * T_LEN * HD];
__device__ float g_v[BH * T_LEN * HD];
__device__ float g_attn[T_LEN * BATCH * EMB]; // [t*4+b][e]

// ---------------------------------------------------------------------------
// GEMM: C[M,N] = A[M,K] (row-major) * B[N,K]^T (row-major) + bias[N]
// mode 0: scatter into g_q/g_k/g_v (q scaled by 0.125). mode 1: write Cout.
// Tiles: 128x128x8, 256 threads, 8x8 micro-tile. M%128==0, N%128==0, K%8==0.
// ---------------------------------------------------------------------------
__global__ void __launch_bounds__(256)
gemm_kernel(const float* __restrict__ A, const float* __restrict__ B,
            const float* __restrict__ bias, float* __restrict__ Cout,
            int M, int N, int K, int mode)
{
    __shared__ float As[8][128];
    __shared__ float Bs[8][128];

    const int tid = threadIdx.x;
    const int tx = tid & 15;        // 0..15
    const int ty = tid >> 4;        // 0..15
    const int row0 = blockIdx.y * 128;
    const int col0 = blockIdx.x * 128;

    const int lr = tid >> 1;        // 0..127
    const int lk = (tid & 1) * 4;   // 0 or 4

    float acc[8][8];
#pragma unroll
    for (int i = 0; i < 8; i++)
#pragma unroll
        for (int j = 0; j < 8; j++) acc[i][j] = 0.0f;

    const float* aPtr = A + (long)(row0 + lr) * K + lk;
    const float* bPtr = B + (long)(col0 + lr) * K + lk;

    for (int k0 = 0; k0 < K; k0 += 8) {
        float4 av = *(const float4*)(aPtr + k0);
        float4 bv = *(const float4*)(bPtr + k0);
        __syncthreads();   // previous iteration's reads complete
        As[lk + 0][lr] = av.x; As[lk + 1][lr] = av.y;
        As[lk + 2][lr] = av.z; As[lk + 3][lr] = av.w;
        Bs[lk + 0][lr] = bv.x; Bs[lk + 1][lr] = bv.y;
        Bs[lk + 2][lr] = bv.z; Bs[lk + 3][lr] = bv.w;
        __syncthreads();

#pragma unroll
        for (int k = 0; k < 8; k++) {
            float a[8], b[8];
            *(float4*)(a)     = *(const float4*)&As[k][ty * 8];
            *(float4*)(a + 4) = *(const float4*)&As[k][ty * 8 + 4];
            *(float4*)(b)     = *(const float4*)&Bs[k][tx * 8];
            *(float4*)(b + 4) = *(const float4*)&Bs[k][tx * 8 + 4];
#pragma unroll
            for (int i = 0; i < 8; i++)
#pragma unroll
                for (int j = 0; j < 8; j++)
                    acc[i][j] = fmaf(a[i], b[j], acc[i][j]);
        }
    }

    // epilogue
#pragma unroll
    for (int i = 0; i < 8; i++) {
        const int m = row0 + ty * 8 + i;
#pragma unroll
        for (int j = 0; j < 8; j++) {
            const int n = col0 + tx * 8 + j;
            float v = acc[i][j] + bias[n];
            if (mode == 0) {
                const int sec = n >> 10;           // 0=q 1=k 2=v
                const int e = n & 1023;
                const int h = e >> 6, d = e & 63;
                const int t = m >> 2, b = m & 3;
                const int bh = b * NH + h;
                const int idx = (bh * T_LEN + t) * HD + d;
                if (sec == 0)      g_q[idx] = v * 0.125f;  // D^-0.5
                else if (sec == 1) g_k[idx] = v;
                else               g_v[idx] = v;
            } else {
                Cout[(long)m * N + n] = v;
            }
        }
    }
}

// ---------------------------------------------------------------------------
// Flash attention with Shaw relative-position bias.
// grid = (16 q-tiles, 64 heads), 256 threads.
// Each block: 64-row q tile, loops 16 k/v tiles of 64 rows.
// Thread (tx,ty) owns rows {ty+16i} and cols {tx+16j} (bank-stride-1 smem).
// ---------------------------------------------------------------------------
__global__ void __launch_bounds__(256)
attn_kernel(const float* __restrict__ relk)
{
    extern __shared__ float sm[];
    float* qs   = sm;                 // [64][65]
    float* ks   = qs   + 64 * 65;     // [64][65]
    float* vs   = ks   + 64 * 65;     // [64][65]
    float* ps   = vs   + 64 * 65;     // [64][65]
    float* rels = ps   + 64 * 65;     // [33][65]
    float* qrs  = rels + 33 * 65;     // [64][33]

    const int tid = threadIdx.x;
    const int tx = tid & 15;
    const int ty = tid >> 4;
    const int bh  = blockIdx.y;
    const int tq0 = blockIdx.x * 64;

    // load q tile (contiguous 4096 floats)
    {
        const float* qb = g_q + (bh * T_LEN + tq0) * HD;
#pragma unroll 2
        for (int i = tid; i < 1024; i += 256) {
            float4 v4 = *(const float4*)(qb + i * 4);
            int r = i >> 4, d = (i & 15) * 4;
            float* p = &qs[r * 65 + d];
            p[0] = v4.x; p[1] = v4.y; p[2] = v4.z; p[3] = v4.w;
        }
    }
    // load relation keys (first 64 channels of each of 33 rows)
    for (int i = tid; i < NREL * 64; i += 256) {
        int j = i >> 6, d = i & 63;
        rels[j * 65 + d] = relk[j * EMB + d];
    }
    __syncthreads();

    // qr[r][j] = q[r] . rel[j]   (q already scaled)
    for (int e = tid; e < 64 * NREL; e += 256) {
        int r = e / NREL, j = e - r * NREL;
        float s = 0.0f;
        const float* qp = &qs[r * 65];
        const float* rp = &rels[j * 65];
#pragma unroll
        for (int d = 0; d < 64; d++) s = fmaf(qp[d], rp[d], s);
        qrs[r * NREL + j] = s;
    }

    float m_r[4], l_r[4], o[4][4];
#pragma unroll
    for (int i = 0; i < 4; i++) {
        m_r[i] = -1e30f; l_r[i] = 0.0f;
#pragma unroll
        for (int j = 0; j < 4; j++) o[i][j] = 0.0f;
    }

    for (int kt = 0; kt < 16; kt++) {
        const int s0 = kt * 64;
        const float* kb = g_k + (bh * T_LEN + s0) * HD;
        const float* vb = g_v + (bh * T_LEN + s0) * HD;

        __syncthreads();   // previous p@v reads of vs done; qr writes visible (first iter)
#pragma unroll 2
        for (int i = tid; i < 1024; i += 256) {
            float4 k4 = *(const float4*)(kb + i * 4);
            float4 v4 = *(const float4*)(vb + i * 4);
            int r = i >> 4, d = (i & 15) * 4;
            float* kp = &ks[r * 65 + d];
            kp[0] = k4.x; kp[1] = k4.y; kp[2] = k4.z; kp[3] = k4.w;
            float* vp = &vs[r * 65 + d];
            vp[0] = v4.x; vp[1] = v4.y; vp[2] = v4.z; vp[3] = v4.w;
        }
        __syncthreads();

        // scores: 4x4 outer-product micro-tile over d
        float sc[4][4];
#pragma unroll
        for (int i = 0; i < 4; i++)
#pragma unroll
            for (int j = 0; j < 4; j++) sc[i][j] = 0.0f;

#pragma unroll 4
        for (int d = 0; d < 64; d++) {
            float a[4], b[4];
#pragma unroll
            for (int i = 0; i < 4; i++) a[i] = qs[(ty + 16 * i) * 65 + d];
#pragma unroll
            for (int j = 0; j < 4; j++) b[j] = ks[(tx + 16 * j) * 65 + d];
#pragma unroll
            for (int i = 0; i < 4; i++)
#pragma unroll
                for (int j = 0; j < 4; j++)
                    sc[i][j] = fmaf(a[i], b[j], sc[i][j]);
        }

        // relative-position bias lookup
#pragma unroll
        for (int i = 0; i < 4; i++) {
            const int rg = tq0 + ty + 16 * i;
#pragma unroll
            for (int j = 0; j < 4; j++) {
                const int sg = s0 + tx + 16 * j;
                int delta = sg - rg;
                delta = min(max(delta, -16), 16);
                sc[i][j] += qrs[(ty + 16 * i) * NREL + delta + 16];
            }
        }

        // online softmax (row reduction across the 16 tx lanes)
#pragma unroll
        for (int i = 0; i < 4; i++) {
            float tm = fmaxf(fmaxf(sc[i][0], sc[i][1]), fmaxf(sc[i][2], sc[i][3]));
#pragma unroll
            for (int off = 8; off >= 1; off >>= 1)
                tm = fmaxf(tm, __shfl_xor_sync(0xffffffffu, tm, off));
            const float mnew = fmaxf(m_r[i], tm);
            const float alpha = __expf(m_r[i] - mnew);
            float rs = 0.0f;
#pragma unroll
            for (int j = 0; j < 4; j++) {
                float p = __expf(sc[i][j] - mnew);
                sc[i][j] = p;
                rs += p;
            }
#pragma unroll
            for (int off = 8; off >= 1; off >>= 1)
                rs += __shfl_xor_sync(0xffffffffu, rs, off);
            l_r[i] = l_r[i] * alpha + rs;
            m_r[i] = mnew;
#pragma unroll
            for (int j = 0; j < 4; j++) o[i][j] *= alpha;
        }

        // stage probabilities
#pragma unroll
        for (int i = 0; i < 4; i++)
#pragma unroll
            for (int j = 0; j < 4; j++)
                ps[(ty + 16 * i) * 65 + tx + 16 * j] = sc[i][j];
        __syncthreads();

        // o += p @ v
#pragma unroll 4
        for (int s = 0; s < 64; s++) {
            float pv[4], vv[4];
#pragma unroll
            for (int i = 0; i < 4; i++) pv[i] = ps[(ty + 16 * i) * 65 + s];
#pragma unroll
            for (int j = 0; j < 4; j++) vv[j] = vs[s * 65 + tx + 16 * j];
#pragma unroll
            for (int i = 0; i < 4; i++)
#pragma unroll
                for (int j = 0; j < 4; j++)
                    o[i][j] = fmaf(pv[i], vv[j], o[i][j]);
        }
    }

    // write attn in [t][b][e] layout
    const int b = bh / NH, h = bh % NH;
#pragma unroll
    for (int i = 0; i < 4; i++) {
        const int t = tq0 + ty + 16 * i;
        const float inv_l = 1.0f / l_r[i];
#pragma unroll
        for (int j = 0; j < 4; j++) {
            const int d = tx + 16 * j;
            g_attn[(t * BATCH + b) * EMB + h * HD + d] = o[i][j] * inv_l;
        }
    }
}

// ---------------------------------------------------------------------------
extern "C" void kernel_launch(void* const* d_in, const int* in_sizes, int n_in,
                              void* d_out, int out_size)
{
    (void)in_sizes; (void)n_in; (void)out_size;
    const float* query = (const float*)d_in[0];   // [T,B,E]
    const float* w_in  = (const float*)d_in[1];   // [3E,E]
    const float* b_in  = (const float*)d_in[2];   // [3E]
    const float* relk  = (const float*)d_in[3];   // [33,E]
    const float* w_out = (const float*)d_in[4];   // [E,E]
    const float* b_out = (const float*)d_in[5];   // [E]
    float* out = (float*)d_out;                   // [T,B,E]

    // 1) fused QKV projection -> head-major q/k/v scratch
    gemm_kernel<<<dim3(3072 / 128, 4096 / 128), 256>>>(
        query, w_in, b_in, nullptr, 4096, 3072, 1024, 0);

    // 2) flash attention with relative bias
    const size_t smem_bytes =
        (size_t)(4 * 64 * 65 + 33 * 65 + 64 * NREL) * sizeof(float);  // ~83.5 KB
    cudaFuncSetAttribute(attn_kernel,
                         cudaFuncAttributeMaxDynamicSharedMemorySize,
                         (int)smem_bytes);
    attn_kernel<<<dim3(16, 64), 256, smem_bytes>>>(relk);

    // 3) output projection
    float* attn_ptr = nullptr;
    cudaGetSymbolAddress((void**)&attn_ptr, g_attn);
    gemm_kernel<<<dim3(1024 / 128, 4096 / 128), 256>>>(
        attn_ptr, w_out, b_out, out, 4096, 1024, 1024, 1);
}

// round 2
// speedup vs baseline: 2.6306x; 2.6306x over previous
#include <cuda_runtime.h>

#define T_LEN 1024
#define BATCH 4
#define EMB   1024
#define NH    16
#define HD    64
#define BH    (BATCH*NH)   // 64
#define NREL  33           // 2L+1

// Scratch (static device arrays: allocation-free per harness rules)
__device__ float g_q[BH * T_LEN * HD];        // [bh][t][d], pre-scaled by 0.125
__device__ float g_k[BH * T_LEN * HD];
__device__ float g_v[BH * T_LEN * HD];
__device__ float g_attn[T_LEN * BATCH * EMB]; // [t*4+b][e]

__device__ __forceinline__ unsigned f2tf(float f) {
    unsigned u;
    asm("cvt.rna.tf32.f32 %0, %1;" : "=r"(u) : "f"(f));
    return u;
}

// D += A @ B  (m16n8k8, tf32 in, fp32 accum). c aliases d.
__device__ __forceinline__ void mma8(float* c, const unsigned* a, const unsigned* b) {
    asm volatile(
        "mma.sync.aligned.m16n8k8.row.col.f32.tf32.tf32.f32 "
        "{%0,%1,%2,%3}, {%4,%5,%6,%7}, {%8,%9}, {%0,%1,%2,%3};\n"
        : "+f"(c[0]), "+f"(c[1]), "+f"(c[2]), "+f"(c[3])
        : "r"(a[0]), "r"(a[1]), "r"(a[2]), "r"(a[3]), "r"(b[0]), "r"(b[1]));
}

// ---------------------------------------------------------------------------
// TC GEMM: C[M,N] = A[M,K] (row-major) * B[N,K]^T (row-major) + bias[N]
// mode 0: scatter into g_q/g_k/g_v (q scaled by 0.125). mode 1: write Cout.
// Block tile 128x128, K-chunk 32, 8 warps (32m x 64n warp tiles).
// ---------------------------------------------------------------------------
__global__ void __launch_bounds__(256)
gemm_tc(const float* __restrict__ A, const float* __restrict__ B,
        const float* __restrict__ bias, float* __restrict__ Cout,
        int M, int N, int K, int mode)
{
    __shared__ unsigned As[128 * 36];   // [m][k], stride 36 (≡4 mod 32)
    __shared__ unsigned Bs[128 * 36];   // [n][k]

    const int tid  = threadIdx.x;
    const int lane = tid & 31;
    const int warp = tid >> 5;
    const int wm   = (warp & 3) * 32;   // warp m-offset within block
    const int wn   = (warp >> 2) * 64;  // warp n-offset within block
    const int row0 = blockIdx.y * 128;
    const int col0 = blockIdx.x * 128;

    const int lr = tid >> 3;            // 0..31
    const int lk = (tid & 7) * 4;       // 0..28

    float acc[2][8][4];
#pragma unroll
    for (int mt = 0; mt < 2; mt++)
#pragma unroll
        for (int nt = 0; nt < 8; nt++)
#pragma unroll
            for (int f = 0; f < 4; f++) acc[mt][nt][f] = 0.0f;

    const float* aP = A + (size_t)row0 * K;
    const float* bP = B + (size_t)col0 * K;

    float4 pa[4], pb[4];
#pragma unroll
    for (int r = 0; r < 4; r++) {
        pa[r] = *(const float4*)(aP + (size_t)(lr + 32 * r) * K + lk);
        pb[r] = *(const float4*)(bP + (size_t)(lr + 32 * r) * K + lk);
    }

    for (int k0 = 0; k0 < K; k0 += 32) {
        __syncthreads();                 // prior chunk's smem reads done
#pragma unroll
        for (int r = 0; r < 4; r++) {
            const int m = lr + 32 * r;
            unsigned* d = &As[m * 36 + lk];
            d[0] = f2tf(pa[r].x); d[1] = f2tf(pa[r].y);
            d[2] = f2tf(pa[r].z); d[3] = f2tf(pa[r].w);
            unsigned* e = &Bs[m * 36 + lk];
            e[0] = f2tf(pb[r].x); e[1] = f2tf(pb[r].y);
            e[2] = f2tf(pb[r].z); e[3] = f2tf(pb[r].w);
        }
        __syncthreads();

        if (k0 + 32 < K) {
#pragma unroll
            for (int r = 0; r < 4; r++) {
                pa[r] = *(const float4*)(aP + (size_t)(lr + 32 * r) * K + k0 + 32 + lk);
                pb[r] = *(const float4*)(bP + (size_t)(lr + 32 * r) * K + k0 + 32 + lk);
            }
        }

#pragma unroll
        for (int ks = 0; ks < 4; ks++) {
            const int kk = ks * 8 + (lane & 3);
            unsigned a[2][4];
#pragma unroll
            for (int mt = 0; mt < 2; mt++) {
                const int m = wm + mt * 16 + (lane >> 2);
                a[mt][0] = As[m * 36 + kk];
                a[mt][1] = As[(m + 8) * 36 + kk];
                a[mt][2] = As[m * 36 + kk + 4];
                a[mt][3] = As[(m + 8) * 36 + kk + 4];
            }
#pragma unroll
            for (int nt = 0; nt < 8; nt++) {
                const int n = wn + nt * 8 + (lane >> 2);
                unsigned b[2];
                b[0] = Bs[n * 36 + kk];
                b[1] = Bs[n * 36 + kk + 4];
                mma8(acc[0][nt], a[0], b);
                mma8(acc[1][nt], a[1], b);
            }
        }
    }

    // epilogue: frag (c0,c1)=(r,c),(r,c+1); (c2,c3)=(r+8,·)
#pragma unroll
    for (int mt = 0; mt < 2; mt++) {
#pragma unroll
        for (int rr = 0; rr < 2; rr++) {
            const int m = row0 + wm + mt * 16 + (lane >> 2) + rr * 8;
#pragma unroll
            for (int nt = 0; nt < 8; nt++) {
#pragma unroll
                for (int cc = 0; cc < 2; cc++) {
                    const int n = col0 + wn + nt * 8 + 2 * (lane & 3) + cc;
                    float v = acc[mt][nt][rr * 2 + cc] + bias[n];
                    if (mode == 0) {
                        const int sec = n >> 10;       // 0=q 1=k 2=v
                        const int e = n & 1023;
                        const int h = e >> 6, d = e & 63;
                        const int t = m >> 2, b = m & 3;
                        const int bh = b * NH + h;
                        const int idx = (bh * T_LEN + t) * HD + d;
                        if (sec == 0)      g_q[idx] = v * 0.125f;
                        else if (sec == 1) g_k[idx] = v;
                        else               g_v[idx] = v;
                    } else {
                        Cout[(size_t)m * N + n] = v;
                    }
                }
            }
        }
    }
}

// ---------------------------------------------------------------------------
// Flash attention with Shaw relative bias, tensor-core QK^T and PV.
// grid = (8 q-tiles of 128, 64 heads), 256 threads (8 warps, 16 q-rows each).
// ---------------------------------------------------------------------------
__global__ void __launch_bounds__(256)
attn_tc(const float* __restrict__ relk)
{
    extern __shared__ float sm[];
    unsigned* Qs = (unsigned*)sm;             // [128][68] tf32
    unsigned* Ks = Qs + 128 * 68;             // [64][68]  tf32
    unsigned* Vs = Ks + 64 * 68;              // [64][72]  tf32 (stride ≡8 mod 32)
    unsigned* Ps = Vs + 64 * 72;              // [128][68] tf32
    float* rels  = (float*)(Ps + 128 * 68);   // [33][68]  fp32
    float* qrs   = rels + 33 * 68;            // [128][33] fp32

    const int tid  = threadIdx.x;
    const int lane = tid & 31;
    const int warp = tid >> 5;
    const int bh   = blockIdx.y;
    const int tq0  = blockIdx.x * 128;
    const int m0   = warp * 16;
    const int r0l  = lane >> 2;               // 0..7

    // load + convert Q tile (128x64)
    {
        const float* qb = g_q + (bh * T_LEN + tq0) * HD;
#pragma unroll 2
        for (int i = tid; i < 2048; i += 256) {
            float4 v4 = *(const float4*)(qb + i * 4);
            const int r = i >> 4, d = (i & 15) * 4;
            unsigned* p = &Qs[r * 68 + d];
            p[0] = f2tf(v4.x); p[1] = f2tf(v4.y);
            p[2] = f2tf(v4.z); p[3] = f2tf(v4.w);
        }
    }
    // relation keys, first 64 channels
    for (int i = tid; i < NREL * 64; i += 256) {
        const int j = i >> 6, d = i & 63;
        rels[j * 68 + d] = relk[j * EMB + d];
    }
    __syncthreads();

    // qr[r][j] = q[r] . rel[j]  (fp32 scalar; small)
    for (int e = tid; e < 128 * NREL; e += 256) {
        const int r = e / NREL, j = e - r * NREL;
        const float* qp = (const float*)&Qs[r * 68];
        const float* rp = &rels[j * 68];
        float s = 0.0f;
#pragma unroll
        for (int d = 0; d < 64; d++) s = fmaf(qp[d], rp[d], s);
        qrs[r * NREL + j] = s;
    }

    float o[8][4];
#pragma unroll
    for (int nt = 0; nt < 8; nt++)
#pragma unroll
        for (int f = 0; f < 4; f++) o[nt][f] = 0.0f;
    float mrow[2] = {-1e30f, -1e30f};
    float lrow[2] = {0.0f, 0.0f};

    for (int kt = 0; kt < 16; kt++) {
        const int s0 = kt * 64;
        __syncthreads();                       // prior PV reads of Ks/Vs done (also orders qrs)
        const float* kb = g_k + (bh * T_LEN + s0) * HD;
        const float* vb = g_v + (bh * T_LEN + s0) * HD;
#pragma unroll 2
        for (int i = tid; i < 1024; i += 256) {
            float4 k4 = *(const float4*)(kb + i * 4);
            float4 v4 = *(const float4*)(vb + i * 4);
            const int r = i >> 4, d = (i & 15) * 4;
            unsigned* kp = &Ks[r * 68 + d];
            kp[0] = f2tf(k4.x); kp[1] = f2tf(k4.y);
            kp[2] = f2tf(k4.z); kp[3] = f2tf(k4.w);
            unsigned* vp = &Vs[r * 72 + d];
            vp[0] = f2tf(v4.x); vp[1] = f2tf(v4.y);
            vp[2] = f2tf(v4.z); vp[3] = f2tf(v4.w);
        }
        __syncthreads();

        // S = Q @ K^T  (warp's 16 rows x 64 cols)
        float s[8][4];
#pragma unroll
        for (int nt = 0; nt < 8; nt++)
#pragma unroll
            for (int f = 0; f < 4; f++) s[nt][f] = 0.0f;

#pragma unroll
        for (int ks = 0; ks < 8; ks++) {
            const int kk = ks * 8 + (lane & 3);
            unsigned a[4];
            const int mr = m0 + r0l;
            a[0] = Qs[mr * 68 + kk];
            a[1] = Qs[(mr + 8) * 68 + kk];
            a[2] = Qs[mr * 68 + kk + 4];
            a[3] = Qs[(mr + 8) * 68 + kk + 4];
#pragma unroll
            for (int nt = 0; nt < 8; nt++) {
                const int n = nt * 8 + r0l;
                unsigned b[2];
                b[0] = Ks[n * 68 + kk];
                b[1] = Ks[n * 68 + kk + 4];
                mma8(s[nt], a, b);
            }
        }

        // bias + online softmax per owned row (2 rows, 4 lanes/row: xor 1,2)
#pragma unroll
        for (int rid = 0; rid < 2; rid++) {
            const int rloc = m0 + r0l + rid * 8;
            const int rg = tq0 + rloc;
            float vals[16];
            float mx = -1e30f;
#pragma unroll
            for (int nt = 0; nt < 8; nt++) {
#pragma unroll
                for (int cc = 0; cc < 2; cc++) {
                    const int sg = s0 + nt * 8 + 2 * (lane & 3) + cc;
                    int delta = min(max(sg - rg, -16), 16) + 16;
                    float v = s[nt][rid * 2 + cc] + qrs[rloc * NREL + delta];
                    vals[nt * 2 + cc] = v;
                    mx = fmaxf(mx, v);
                }
            }
            mx = fmaxf(mx, __shfl_xor_sync(0xffffffffu, mx, 1));
            mx = fmaxf(mx, __shfl_xor_sync(0xffffffffu, mx, 2));
            const float mnew = fmaxf(mrow[rid], mx);
            const float alpha = __expf(mrow[rid] - mnew);
            float rs = 0.0f;
#pragma unroll
            for (int j = 0; j < 16; j++) {
                vals[j] = __expf(vals[j] - mnew);
                rs += vals[j];
            }
            rs += __shfl_xor_sync(0xffffffffu, rs, 1);
            rs += __shfl_xor_sync(0xffffffffu, rs, 2);
            lrow[rid] = lrow[rid] * alpha + rs;
            mrow[rid] = mnew;
#pragma unroll
            for (int nt = 0; nt < 8; nt++) {
                o[nt][rid * 2]     *= alpha;
                o[nt][rid * 2 + 1] *= alpha;
            }
            // stage P (tf32) — own warp rows only
#pragma unroll
            for (int nt = 0; nt < 8; nt++) {
                const int c = nt * 8 + 2 * (lane & 3);
                uint2 pw = make_uint2(f2tf(vals[nt * 2]), f2tf(vals[nt * 2 + 1]));
                *(uint2*)&Ps[rloc * 68 + c] = pw;
            }
        }
        __syncwarp();   // P written/read within this warp only

        // O += P @ V
#pragma unroll
        for (int ks = 0; ks < 8; ks++) {
            const int kk = ks * 8 + (lane & 3);
            unsigned a[4];
            const int mr = m0 + r0l;
            a[0] = Ps[mr * 68 + kk];
            a[1] = Ps[(mr + 8) * 68 + kk];
            a[2] = Ps[mr * 68 + kk + 4];
            a[3] = Ps[(mr + 8) * 68 + kk + 4];
#pragma unroll
            for (int nt = 0; nt < 8; nt++) {
                const int n = nt * 8 + r0l;
                unsigned b[2];
                b[0] = Vs[kk * 72 + n];
                b[1] = Vs[(kk + 4) * 72 + n];
                mma8(o[nt], a, b);
            }
        }
    }

    // write attn in [t][b][e] layout
    const int b = bh >> 4, h = bh & 15;
#pragma unroll
    for (int rid = 0; rid < 2; rid++) {
        const int t = tq0 + m0 + r0l + rid * 8;
        const float inv = 1.0f / lrow[rid];
#pragma unroll
        for (int nt = 0; nt < 8; nt++) {
            const int d = nt * 8 + 2 * (lane & 3);
            float2 w = make_float2(o[nt][rid * 2] * inv, o[nt][rid * 2 + 1] * inv);
            *(float2*)&g_attn[(t * BATCH + b) * EMB + h * HD + d] = w;
        }
    }
}

// ---------------------------------------------------------------------------
extern "C" void kernel_launch(void* const* d_in, const int* in_sizes, int n_in,
                              void* d_out, int out_size)
{
    (void)in_sizes; (void)n_in; (void)out_size;
    const float* query = (const float*)d_in[0];   // [T,B,E]
    const float* w_in  = (const float*)d_in[1];   // [3E,E]
    const float* b_in  = (const float*)d_in[2];   // [3E]
    const float* relk  = (const float*)d_in[3];   // [33,E]
    const float* w_out = (const float*)d_in[4];   // [E,E]
    const float* b_out = (const float*)d_in[5];   // [E]
    float* out = (float*)d_out;                   // [T,B,E]

    // 1) fused QKV projection -> head-major q/k/v scratch (tf32 TC)
    gemm_tc<<<dim3(3072 / 128, 4096 / 128), 256>>>(
        query, w_in, b_in, nullptr, 4096, 3072, 1024, 0);

    // 2) flash attention with relative bias (tf32 TC)
    const size_t smem_bytes =
        (size_t)(128 * 68 + 64 * 68 + 64 * 72 + 128 * 68 + 33 * 68 + 128 * NREL)
        * sizeof(float);   // ~131 KB
    cudaFuncSetAttribute(attn_tc,
                         cudaFuncAttributeMaxDynamicSharedMemorySize,
                         (int)smem_bytes);
    attn_tc<<<dim3(8, 64), 256, smem_bytes>>>(relk);

    // 3) output projection (tf32 TC)
    float* attn_ptr = nullptr;
    cudaGetSymbolAddress((void**)&attn_ptr, g_attn);
    gemm_tc<<<dim3(1024 / 128, 4096 / 128), 256>>>(
        attn_ptr, w_out, b_out, out, 4096, 1024, 1024, 1);
}

// round 3
// speedup vs baseline: 2.6827x; 1.0198x over previous
#include <cuda_runtime.h>

#define T_LEN 1024
#define BATCH 4
#define EMB   1024
#define NH    16
#define HD    64
#define BH    (BATCH*NH)   // 64
#define NREL  33           // 2L+1

// Scratch (static device arrays: allocation-free per harness rules)
__device__ float g_q[BH * T_LEN * HD];        // [bh][t][d], pre-scaled by 0.125
__device__ float g_k[BH * T_LEN * HD];
__device__ float g_v[BH * T_LEN * HD];
__device__ float g_attn[T_LEN * BATCH * EMB]; // [t*4+b][e]

__device__ __forceinline__ unsigned f2tf(float f) {
    unsigned u;
    asm("cvt.rna.tf32.f32 %0, %1;" : "=r"(u) : "f"(f));
    return u;
}

// D += A @ B  (m16n8k8, tf32 in, fp32 accum). c aliases d.
__device__ __forceinline__ void mma8(float* c, const unsigned* a, const unsigned* b) {
    asm volatile(
        "mma.sync.aligned.m16n8k8.row.col.f32.tf32.tf32.f32 "
        "{%0,%1,%2,%3}, {%4,%5,%6,%7}, {%8,%9}, {%0,%1,%2,%3};\n"
        : "+f"(c[0]), "+f"(c[1]), "+f"(c[2]), "+f"(c[3])
        : "r"(a[0]), "r"(a[1]), "r"(a[2]), "r"(a[3]), "r"(b[0]), "r"(b[1]));
}

// ---------------------------------------------------------------------------
// TC GEMM: C[M,N] = A[M,K] (row-major) * B[N,K]^T (row-major) + bias[N]
// mode 0: scatter into g_q/g_k/g_v (q scaled by 0.125). mode 1: write Cout.
// Block tile 128x128, K-chunk 32, 8 warps (32m x 64n warp tiles).
// 2-stage smem pipeline: ONE barrier per chunk, global prefetch overlaps MMA.
// ---------------------------------------------------------------------------
#define GSTG (128 * 36)

__global__ void __launch_bounds__(256)
gemm_tc(const float* __restrict__ A, const float* __restrict__ B,
        const float* __restrict__ bias, float* __restrict__ Cout,
        int M, int N, int K, int mode)
{
    extern __shared__ unsigned sh[];
    unsigned* As = sh;               // [2][128*36], stride 36 (≡4 mod 32)
    unsigned* Bs = sh + 2 * GSTG;    // [2][128*36]

    const int tid  = threadIdx.x;
    const int lane = tid & 31;
    const int warp = tid >> 5;
    const int wm   = (warp & 3) * 32;   // warp m-offset within block
    const int wn   = (warp >> 2) * 64;  // warp n-offset within block
    const int row0 = blockIdx.y * 128;
    const int col0 = blockIdx.x * 128;

    const int lr = tid >> 3;            // 0..31
    const int lk = (tid & 7) * 4;       // 0..28

    float acc[2][8][4];
#pragma unroll
    for (int mt = 0; mt < 2; mt++)
#pragma unroll
        for (int nt = 0; nt < 8; nt++)
#pragma unroll
            for (int f = 0; f < 4; f++) acc[mt][nt][f] = 0.0f;

    const float* aP = A + (size_t)row0 * K;
    const float* bP = B + (size_t)col0 * K;

    float4 pa[4], pb[4];
#pragma unroll
    for (int r = 0; r < 4; r++) {
        pa[r] = *(const float4*)(aP + (size_t)(lr + 32 * r) * K + lk);
        pb[r] = *(const float4*)(bP + (size_t)(lr + 32 * r) * K + lk);
    }
#pragma unroll
    for (int r = 0; r < 4; r++) {
        unsigned* d = &As[(lr + 32 * r) * 36 + lk];
        d[0] = f2tf(pa[r].x); d[1] = f2tf(pa[r].y);
        d[2] = f2tf(pa[r].z); d[3] = f2tf(pa[r].w);
        unsigned* e = &Bs[(lr + 32 * r) * 36 + lk];
        e[0] = f2tf(pb[r].x); e[1] = f2tf(pb[r].y);
        e[2] = f2tf(pb[r].z); e[3] = f2tf(pb[r].w);
    }
    __syncthreads();

    const int nC = K >> 5;
    for (int c = 0; c < nC; c++) {
        unsigned* Ac = As + (c & 1) * GSTG;
        unsigned* Bc = Bs + (c & 1) * GSTG;
        unsigned* An = As + ((c & 1) ^ 1) * GSTG;
        unsigned* Bn = Bs + ((c & 1) ^ 1) * GSTG;

        const bool more = (c + 1 < nC);
        if (more) {
            const int ko = (c + 1) * 32 + lk;
#pragma unroll
            for (int r = 0; r < 4; r++) {
                pa[r] = *(const float4*)(aP + (size_t)(lr + 32 * r) * K + ko);
                pb[r] = *(const float4*)(bP + (size_t)(lr + 32 * r) * K + ko);
            }
        }

#pragma unroll
        for (int ks = 0; ks < 4; ks++) {
            const int kk = ks * 8 + (lane & 3);
            unsigned a[2][4];
#pragma unroll
            for (int mt = 0; mt < 2; mt++) {
                const int m = wm + mt * 16 + (lane >> 2);
                a[mt][0] = Ac[m * 36 + kk];
                a[mt][1] = Ac[(m + 8) * 36 + kk];
                a[mt][2] = Ac[m * 36 + kk + 4];
                a[mt][3] = Ac[(m + 8) * 36 + kk + 4];
            }
#pragma unroll
            for (int nt = 0; nt < 8; nt++) {
                const int n = wn + nt * 8 + (lane >> 2);
                unsigned b[2];
                b[0] = Bc[n * 36 + kk];
                b[1] = Bc[n * 36 + kk + 4];
                mma8(acc[0][nt], a[0], b);
                mma8(acc[1][nt], a[1], b);
            }
        }

        if (more) {
#pragma unroll
            for (int r = 0; r < 4; r++) {
                unsigned* d = &An[(lr + 32 * r) * 36 + lk];
                d[0] = f2tf(pa[r].x); d[1] = f2tf(pa[r].y);
                d[2] = f2tf(pa[r].z); d[3] = f2tf(pa[r].w);
                unsigned* e = &Bn[(lr + 32 * r) * 36 + lk];
                e[0] = f2tf(pb[r].x); e[1] = f2tf(pb[r].y);
                e[2] = f2tf(pb[r].z); e[3] = f2tf(pb[r].w);
            }
        }
        __syncthreads();
    }

    // epilogue: frag (c0,c1)=(r,c),(r,c+1); (c2,c3)=(r+8,·)
#pragma unroll
    for (int mt = 0; mt < 2; mt++) {
#pragma unroll
        for (int rr = 0; rr < 2; rr++) {
            const int m = row0 + wm + mt * 16 + (lane >> 2) + rr * 8;
#pragma unroll
            for (int nt = 0; nt < 8; nt++) {
#pragma unroll
                for (int cc = 0; cc < 2; cc++) {
                    const int n = col0 + wn + nt * 8 + 2 * (lane & 3) + cc;
                    float v = acc[mt][nt][rr * 2 + cc] + bias[n];
                    if (mode == 0) {
                        const int sec = n >> 10;       // 0=q 1=k 2=v
                        const int e = n & 1023;
                        const int h = e >> 6, d = e & 63;
                        const int t = m >> 2, b = m & 3;
                        const int bh = b * NH + h;
                        const int idx = (bh * T_LEN + t) * HD + d;
                        if (sec == 0)      g_q[idx] = v * 0.125f;
                        else if (sec == 1) g_k[idx] = v;
                        else               g_v[idx] = v;
                    } else {
                        Cout[(size_t)m * N + n] = v;
                    }
                }
            }
        }
    }
}

// ---------------------------------------------------------------------------
// Flash attention with Shaw relative bias, tensor-core QK^T and PV.
// grid = (8 q-tiles of 128, 64 heads), 256 threads (8 warps, 16 q-rows each).
// 2-stage K/V smem pipeline: one barrier per k-tile, prefetch overlaps MMA.
// ---------------------------------------------------------------------------
__global__ void __launch_bounds__(256)
attn_tc(const float* __restrict__ relk)
{
    extern __shared__ float sm[];
    unsigned* Qs = (unsigned*)sm;             // [128][68] tf32
    unsigned* Ks = Qs + 128 * 68;             // [2][64][68] tf32
    unsigned* Vs = Ks + 2 * 64 * 68;          // [2][64][72] tf32
    unsigned* Ps = Vs + 2 * 64 * 72;          // [128][68] tf32
    float* rels  = (float*)(Ps + 128 * 68);   // [33][68]  fp32
    float* qrs   = rels + 33 * 68;            // [128][33] fp32

    const int tid  = threadIdx.x;
    const int lane = tid & 31;
    const int warp = tid >> 5;
    const int bh   = blockIdx.y;
    const int tq0  = blockIdx.x * 128;
    const int m0   = warp * 16;
    const int r0l  = lane >> 2;               // 0..7

    // load + convert Q tile (128x64)
    {
        const float* qb = g_q + (bh * T_LEN + tq0) * HD;
#pragma unroll 2
        for (int i = tid; i < 2048; i += 256) {
            float4 v4 = *(const float4*)(qb + i * 4);
            const int r = i >> 4, d = (i & 15) * 4;
            unsigned* p = &Qs[r * 68 + d];
            p[0] = f2tf(v4.x); p[1] = f2tf(v4.y);
            p[2] = f2tf(v4.z); p[3] = f2tf(v4.w);
        }
    }
    // relation keys, first 64 channels
    for (int i = tid; i < NREL * 64; i += 256) {
        const int j = i >> 6, d = i & 63;
        rels[j * 68 + d] = relk[j * EMB + d];
    }
    __syncthreads();

    // qr[r][j] = q[r] . rel[j]  (fp32 scalar; small)
    for (int e = tid; e < 128 * NREL; e += 256) {
        const int r = e / NREL, j = e - r * NREL;
        const float* qp = (const float*)&Qs[r * 68];
        const float* rp = &rels[j * 68];
        float s = 0.0f;
#pragma unroll
        for (int d = 0; d < 64; d++) s = fmaf(qp[d], rp[d], s);
        qrs[r * NREL + j] = s;
    }

    // preload k-tile 0 into registers and stage 0
    const float* kbase = g_k + (size_t)bh * T_LEN * HD;
    const float* vbase = g_v + (size_t)bh * T_LEN * HD;
    float4 pk[4], pv[4];
#pragma unroll
    for (int it = 0; it < 4; it++) {
        const int i = tid + 256 * it;
        pk[it] = *(const float4*)(kbase + i * 4);
        pv[it] = *(const float4*)(vbase + i * 4);
    }
#pragma unroll
    for (int it = 0; it < 4; it++) {
        const int i = tid + 256 * it;
        const int r = i >> 4, d = (i & 15) * 4;
        unsigned* kp = &Ks[r * 68 + d];
        kp[0] = f2tf(pk[it].x); kp[1] = f2tf(pk[it].y);
        kp[2] = f2tf(pk[it].z); kp[3] = f2tf(pk[it].w);
        unsigned* vp = &Vs[r * 72 + d];
        vp[0] = f2tf(pv[it].x); vp[1] = f2tf(pv[it].y);
        vp[2] = f2tf(pv[it].z); vp[3] = f2tf(pv[it].w);
    }

    float o[8][4];
#pragma unroll
    for (int nt = 0; nt < 8; nt++)
#pragma unroll
        for (int f = 0; f < 4; f++) o[nt][f] = 0.0f;
    float mrow[2] = {-1e30f, -1e30f};
    float lrow[2] = {0.0f, 0.0f};

    __syncthreads();   // stage 0 + qrs visible

    for (int kt = 0; kt < 16; kt++) {
        const int s0 = kt * 64;
        unsigned* Kc = Ks + (kt & 1) * (64 * 68);
        unsigned* Vc = Vs + (kt & 1) * (64 * 72);
        unsigned* Kn = Ks + ((kt & 1) ^ 1) * (64 * 68);
        unsigned* Vn = Vs + ((kt & 1) ^ 1) * (64 * 72);

        const bool more = (kt + 1 < 16);
        if (more) {
            const float* kb = kbase + (size_t)(s0 + 64) * HD;
            const float* vb = vbase + (size_t)(s0 + 64) * HD;
#pragma unroll
            for (int it = 0; it < 4; it++) {
                const int i = tid + 256 * it;
                pk[it] = *(const float4*)(kb + i * 4);
                pv[it] = *(const float4*)(vb + i * 4);
            }
        }

        // S = Q @ K^T  (warp's 16 rows x 64 cols)
        float s[8][4];
#pragma unroll
        for (int nt = 0; nt < 8; nt++)
#pragma unroll
            for (int f = 0; f < 4; f++) s[nt][f] = 0.0f;

#pragma unroll
        for (int ks = 0; ks < 8; ks++) {
            const int kk = ks * 8 + (lane & 3);
            unsigned a[4];
            const int mr = m0 + r0l;
            a[0] = Qs[mr * 68 + kk];
            a[1] = Qs[(mr + 8) * 68 + kk];
            a[2] = Qs[mr * 68 + kk + 4];
            a[3] = Qs[(mr + 8) * 68 + kk + 4];
#pragma unroll
            for (int nt = 0; nt < 8; nt++) {
                const int n = nt * 8 + r0l;
                unsigned b[2];
                b[0] = Kc[n * 68 + kk];
                b[1] = Kc[n * 68 + kk + 4];
                mma8(s[nt], a, b);
            }
        }

        // bias + online softmax per owned row (2 rows, 4 lanes/row: xor 1,2)
#pragma unroll
        for (int rid = 0; rid < 2; rid++) {
            const int rloc = m0 + r0l + rid * 8;
            const int rg = tq0 + rloc;
            float vals[16];
            float mx = -1e30f;
#pragma unroll
            for (int nt = 0; nt < 8; nt++) {
#pragma unroll
                for (int cc = 0; cc < 2; cc++) {
                    const int sg = s0 + nt * 8 + 2 * (lane & 3) + cc;
                    int delta = min(max(sg - rg, -16), 16) + 16;
                    float v = s[nt][rid * 2 + cc] + qrs[rloc * NREL + delta];
                    vals[nt * 2 + cc] = v;
                    mx = fmaxf(mx, v);
                }
            }
            mx = fmaxf(mx, __shfl_xor_sync(0xffffffffu, mx, 1));
            mx = fmaxf(mx, __shfl_xor_sync(0xffffffffu, mx, 2));
            const float mnew = fmaxf(mrow[rid], mx);
            const float alpha = __expf(mrow[rid] - mnew);
            float rs = 0.0f;
#pragma unroll
            for (int j = 0; j < 16; j++) {
                vals[j] = __expf(vals[j] - mnew);
                rs += vals[j];
            }
            rs += __shfl_xor_sync(0xffffffffu, rs, 1);
            rs += __shfl_xor_sync(0xffffffffu, rs, 2);
            lrow[rid] = lrow[rid] * alpha + rs;
            mrow[rid] = mnew;
#pragma unroll
            for (int nt = 0; nt < 8; nt++) {
                o[nt][rid * 2]     *= alpha;
                o[nt][rid * 2 + 1] *= alpha;
            }
            // stage P (tf32) — own warp rows only
#pragma unroll
            for (int nt = 0; nt < 8; nt++) {
                const int c = nt * 8 + 2 * (lane & 3);
                uint2 pw = make_uint2(f2tf(vals[nt * 2]), f2tf(vals[nt * 2 + 1]));
                *(uint2*)&Ps[rloc * 68 + c] = pw;
            }
        }
        __syncwarp();   // P written/read within this warp only

        // O += P @ V
#pragma unroll
        for (int ks = 0; ks < 8; ks++) {
            const int kk = ks * 8 + (lane & 3);
            unsigned a[4];
            const int mr = m0 + r0l;
            a[0] = Ps[mr * 68 + kk];
            a[1] = Ps[(mr + 8) * 68 + kk];
            a[2] = Ps[mr * 68 + kk + 4];
            a[3] = Ps[(mr + 8) * 68 + kk + 4];
#pragma unroll
            for (int nt = 0; nt < 8; nt++) {
                const int n = nt * 8 + r0l;
                unsigned b[2];
                b[0] = Vc[kk * 72 + n];
                b[1] = Vc[(kk + 4) * 72 + n];
                mma8(o[nt], a, b);
            }
        }

        // store prefetched next tile into alternate stage
        if (more) {
#pragma unroll
            for (int it = 0; it < 4; it++) {
                const int i = tid + 256 * it;
                const int r = i >> 4, d = (i & 15) * 4;
                unsigned* kp = &Kn[r * 68 + d];
                kp[0] = f2tf(pk[it].x); kp[1] = f2tf(pk[it].y);
                kp[2] = f2tf(pk[it].z); kp[3] = f2tf(pk[it].w);
                unsigned* vp = &Vn[r * 72 + d];
                vp[0] = f2tf(pv[it].x); vp[1] = f2tf(pv[it].y);
                vp[2] = f2tf(pv[it].z); vp[3] = f2tf(pv[it].w);
            }
        }
        __syncthreads();
    }

    // write attn in [t][b][e] layout
    const int b = bh >> 4, h = bh & 15;
#pragma unroll
    for (int rid = 0; rid < 2; rid++) {
        const int t = tq0 + m0 + r0l + rid * 8;
        const float inv = 1.0f / lrow[rid];
#pragma unroll
        for (int nt = 0; nt < 8; nt++) {
            const int d = nt * 8 + 2 * (lane & 3);
            float2 w = make_float2(o[nt][rid * 2] * inv, o[nt][rid * 2 + 1] * inv);
            *(float2*)&g_attn[(t * BATCH + b) * EMB + h * HD + d] = w;
        }
    }
}

// ---------------------------------------------------------------------------
extern "C" void kernel_launch(void* const* d_in, const int* in_sizes, int n_in,
                              void* d_out, int out_size)
{
    (void)in_sizes; (void)n_in; (void)out_size;
    const float* query = (const float*)d_in[0];   // [T,B,E]
    const float* w_in  = (const float*)d_in[1];   // [3E,E]
    const float* b_in  = (const float*)d_in[2];   // [3E]
    const float* relk  = (const float*)d_in[3];   // [33,E]
    const float* w_out = (const float*)d_in[4];   // [E,E]
    const float* b_out = (const float*)d_in[5];   // [E]
    float* out = (float*)d_out;                   // [T,B,E]

    const size_t gemm_smem = (size_t)4 * GSTG * sizeof(unsigned);  // 73728 B
    cudaFuncSetAttribute(gemm_tc,
                         cudaFuncAttributeMaxDynamicSharedMemorySize,
                         (int)gemm_smem);

    // 1) fused QKV projection -> head-major q/k/v scratch (tf32 TC)
    gemm_tc<<<dim3(3072 / 128, 4096 / 128), 256, gemm_smem>>>(
        query, w_in, b_in, nullptr, 4096, 3072, 1024, 0);

    // 2) flash attention with relative bias (tf32 TC, 2-stage K/V pipeline)
    const size_t attn_smem =
        (size_t)(128 * 68 + 2 * 64 * 68 + 2 * 64 * 72 + 128 * 68
                 + 33 * 68 + 128 * NREL) * sizeof(float);  // ~167 KB
    cudaFuncSetAttribute(attn_tc,
                         cudaFuncAttributeMaxDynamicSharedMemorySize,
                         (int)attn_smem);
    attn_tc<<<dim3(8, 64), 256, attn_smem>>>(relk);

    // 3) output projection (tf32 TC)
    float* attn_ptr = nullptr;
    cudaGetSymbolAddress((void**)&attn_ptr, g_attn);
    gemm_tc<<<dim3(1024 / 128, 4096 / 128), 256, gemm_smem>>>(
        attn_ptr, w_out, b_out, out, 4096, 1024, 1024, 1);
}

// round 4
// speedup vs baseline: 2.9978x; 1.1174x over previous
#include <cuda_runtime.h>

#define T_LEN 1024
#define BATCH 4
#define EMB   1024
#define NH    16
#define HD    64
#define BH    (BATCH*NH)   // 64
#define NREL  33           // 2L+1

// Scratch (static device arrays: allocation-free per harness rules)
__device__ float g_q[BH * T_LEN * HD];        // tf32 bits, pre-scaled by 0.125
__device__ float g_k[BH * T_LEN * HD];        // tf32 bits
__device__ float g_v[BH * T_LEN * HD];        // tf32 bits
__device__ float g_attn[T_LEN * BATCH * EMB]; // tf32 bits, [t*4+b][e]
__device__ float g_qin[4096 * 1024];          // tf32(query)
__device__ float g_win[3072 * 1024];          // tf32(w_in)
__device__ float g_wout[1024 * 1024];         // tf32(w_out)

__device__ __forceinline__ unsigned f2tf(float f) {
    unsigned u;
    asm("cvt.rna.tf32.f32 %0, %1;" : "=r"(u) : "f"(f));
    return u;
}

// D += A @ B  (m16n8k8, tf32 in, fp32 accum). c aliases d.
__device__ __forceinline__ void mma8(float* c, const unsigned* a, const unsigned* b) {
    asm volatile(
        "mma.sync.aligned.m16n8k8.row.col.f32.tf32.tf32.f32 "
        "{%0,%1,%2,%3}, {%4,%5,%6,%7}, {%8,%9}, {%0,%1,%2,%3};\n"
        : "+f"(c[0]), "+f"(c[1]), "+f"(c[2]), "+f"(c[3])
        : "r"(a[0]), "r"(a[1]), "r"(a[2]), "r"(a[3]), "r"(b[0]), "r"(b[1]));
}

// ---------------------------------------------------------------------------
// Elementwise fp32 -> tf32(rna) pre-conversion (bits stored in float array).
// ---------------------------------------------------------------------------
__global__ void __launch_bounds__(256)
cvt_tf32(const float* __restrict__ in, float* __restrict__ out_, int n4)
{
    const int i = blockIdx.x * 256 + threadIdx.x;
    if (i < n4) {
        float4 v = ((const float4*)in)[i];
        uint4 u = make_uint4(f2tf(v.x), f2tf(v.y), f2tf(v.z), f2tf(v.w));
        ((uint4*)out_)[i] = u;
    }
}

// ---------------------------------------------------------------------------
// TC GEMM: C[M,N] = A[M,K] * B[N,K]^T + bias[N].  A,B hold tf32 bit patterns.
// mode 0: scatter tf32-rounded q/k/v (q scaled). mode 1: write fp32 Cout.
// Block tile 128x128, K-chunk 32, 8 warps. 2-stage smem pipeline, 2 CTAs/SM.
// ---------------------------------------------------------------------------
#define GSTG (128 * 36)

__global__ void __launch_bounds__(256, 2)
gemm_tc(const float* __restrict__ A, const float* __restrict__ B,
        const float* __restrict__ bias, float* __restrict__ Cout,
        int M, int N, int K, int mode)
{
    extern __shared__ unsigned sh[];
    unsigned* As = sh;               // [2][128*36], stride 36 (≡4 mod 32)
    unsigned* Bs = sh + 2 * GSTG;

    const int tid  = threadIdx.x;
    const int lane = tid & 31;
    const int warp = tid >> 5;
    const int wm   = (warp & 3) * 32;
    const int wn   = (warp >> 2) * 64;
    const int row0 = blockIdx.y * 128;
    const int col0 = blockIdx.x * 128;

    const int lr = tid >> 3;            // 0..31
    const int lk = (tid & 7) * 4;       // 0..28

    float acc[2][8][4];
#pragma unroll
    for (int mt = 0; mt < 2; mt++)
#pragma unroll
        for (int nt = 0; nt < 8; nt++)
#pragma unroll
            for (int f = 0; f < 4; f++) acc[mt][nt][f] = 0.0f;

    const unsigned* aP = (const unsigned*)A + (size_t)row0 * K;
    const unsigned* bP = (const unsigned*)B + (size_t)col0 * K;

    uint4 pa[4], pb[4];
#pragma unroll
    for (int r = 0; r < 4; r++) {
        pa[r] = *(const uint4*)(aP + (size_t)(lr + 32 * r) * K + lk);
        pb[r] = *(const uint4*)(bP + (size_t)(lr + 32 * r) * K + lk);
    }
#pragma unroll
    for (int r = 0; r < 4; r++) {
        *(uint4*)&As[(lr + 32 * r) * 36 + lk] = pa[r];
        *(uint4*)&Bs[(lr + 32 * r) * 36 + lk] = pb[r];
    }
    __syncthreads();

    const int nC = K >> 5;
    for (int c = 0; c < nC; c++) {
        unsigned* Ac = As + (c & 1) * GSTG;
        unsigned* Bc = Bs + (c & 1) * GSTG;
        unsigned* An = As + ((c & 1) ^ 1) * GSTG;
        unsigned* Bn = Bs + ((c & 1) ^ 1) * GSTG;

        const bool more = (c + 1 < nC);
        if (more) {
            const int ko = (c + 1) * 32 + lk;
#pragma unroll
            for (int r = 0; r < 4; r++) {
                pa[r] = *(const uint4*)(aP + (size_t)(lr + 32 * r) * K + ko);
                pb[r] = *(const uint4*)(bP + (size_t)(lr + 32 * r) * K + ko);
            }
        }

#pragma unroll
        for (int ks = 0; ks < 4; ks++) {
            const int kk = ks * 8 + (lane & 3);
            unsigned a[2][4];
#pragma unroll
            for (int mt = 0; mt < 2; mt++) {
                const int m = wm + mt * 16 + (lane >> 2);
                a[mt][0] = Ac[m * 36 + kk];
                a[mt][1] = Ac[(m + 8) * 36 + kk];
                a[mt][2] = Ac[m * 36 + kk + 4];
                a[mt][3] = Ac[(m + 8) * 36 + kk + 4];
            }
#pragma unroll
            for (int nt = 0; nt < 8; nt++) {
                const int n = wn + nt * 8 + (lane >> 2);
                unsigned b[2];
                b[0] = Bc[n * 36 + kk];
                b[1] = Bc[n * 36 + kk + 4];
                mma8(acc[0][nt], a[0], b);
                mma8(acc[1][nt], a[1], b);
            }
        }

        if (more) {
#pragma unroll
            for (int r = 0; r < 4; r++) {
                *(uint4*)&An[(lr + 32 * r) * 36 + lk] = pa[r];
                *(uint4*)&Bn[(lr + 32 * r) * 36 + lk] = pb[r];
            }
        }
        __syncthreads();
    }

    // epilogue
#pragma unroll
    for (int mt = 0; mt < 2; mt++) {
#pragma unroll
        for (int rr = 0; rr < 2; rr++) {
            const int m = row0 + wm + mt * 16 + (lane >> 2) + rr * 8;
#pragma unroll
            for (int nt = 0; nt < 8; nt++) {
#pragma unroll
                for (int cc = 0; cc < 2; cc++) {
                    const int n = col0 + wn + nt * 8 + 2 * (lane & 3) + cc;
                    float v = acc[mt][nt][rr * 2 + cc] + bias[n];
                    if (mode == 0) {
                        const int sec = n >> 10;       // 0=q 1=k 2=v
                        const int e = n & 1023;
                        const int h = e >> 6, d = e & 63;
                        const int t = m >> 2, b = m & 3;
                        const int bh = b * NH + h;
                        const int idx = (bh * T_LEN + t) * HD + d;
                        if (sec == 0)      g_q[idx] = __uint_as_float(f2tf(v * 0.125f));
                        else if (sec == 1) g_k[idx] = __uint_as_float(f2tf(v));
                        else               g_v[idx] = __uint_as_float(f2tf(v));
                    } else {
                        Cout[(size_t)m * N + n] = v;
                    }
                }
            }
        }
    }
}

// ---------------------------------------------------------------------------
// Flash attention with Shaw relative bias, tensor-core QK^T and PV.
// grid = (16 q-tiles of 64, 64 heads), 128 threads (4 warps, 16 q-rows each).
// Inputs already tf32-rounded. 85KB smem -> 2 CTAs/SM.
// ---------------------------------------------------------------------------
__global__ void __launch_bounds__(128)
attn_tc(const float* __restrict__ relk)
{
    extern __shared__ float sm[];
    unsigned* Qs = (unsigned*)sm;             // [64][68] tf32
    unsigned* Ks = Qs + 64 * 68;              // [64][68]
    unsigned* Vs = Ks + 64 * 68;              // [64][68]
    unsigned* Ps = Vs + 64 * 68;              // [64][68]
    float* rels  = (float*)(Ps + 64 * 68);    // [33][68] fp32
    float* qrs   = rels + 33 * 68;            // [64][33] fp32

    const int tid  = threadIdx.x;
    const int lane = tid & 31;
    const int warp = tid >> 5;                // 0..3
    const int bh   = blockIdx.y;
    const int tq0  = blockIdx.x * 64;
    const int m0   = warp * 16;
    const int r0l  = lane >> 2;               // 0..7

    // load Q tile (64x64, already tf32)
    {
        const uint4* qb = (const uint4*)(g_q + (size_t)(bh * T_LEN + tq0) * HD);
#pragma unroll 2
        for (int i = tid; i < 1024; i += 128) {
            uint4 v4 = qb[i];
            *(uint4*)&Qs[(i >> 4) * 68 + (i & 15) * 4] = v4;
        }
    }
    // relation keys, first 64 channels
    for (int i = tid; i < NREL * 64; i += 128) {
        const int j = i >> 6, d = i & 63;
        rels[j * 68 + d] = relk[j * EMB + d];
    }
    __syncthreads();

    // qr[r][j] = q[r] . rel[j]
    for (int e = tid; e < 64 * NREL; e += 128) {
        const int r = e / NREL, j = e - r * NREL;
        const float* qp = (const float*)&Qs[r * 68];
        const float* rp = &rels[j * 68];
        float s = 0.0f;
#pragma unroll
        for (int d = 0; d < 64; d++) s = fmaf(qp[d], rp[d], s);
        qrs[r * NREL + j] = s;
    }

    const uint4* kbase = (const uint4*)(g_k + (size_t)bh * T_LEN * HD);
    const uint4* vbase = (const uint4*)(g_v + (size_t)bh * T_LEN * HD);

    // prefetch tile 0 (8 uint4 per array per thread)
    uint4 pk[8], pv[8];
#pragma unroll
    for (int it = 0; it < 8; it++) {
        const int i = tid + 128 * it;
        pk[it] = kbase[i];
        pv[it] = vbase[i];
    }

    float o[8][4];
#pragma unroll
    for (int nt = 0; nt < 8; nt++)
#pragma unroll
        for (int f = 0; f < 4; f++) o[nt][f] = 0.0f;
    float mrow[2] = {-1e30f, -1e30f};
    float lrow[2] = {0.0f, 0.0f};

    __syncthreads();   // qrs visible

    for (int kt = 0; kt < 16; kt++) {
        const int s0 = kt * 64;

        // store prefetched tile (prior compute finished at loop-end barrier)
#pragma unroll
        for (int it = 0; it < 8; it++) {
            const int i = tid + 128 * it;
            const int r = i >> 4, d = (i & 15) * 4;
            *(uint4*)&Ks[r * 68 + d] = pk[it];
            *(uint4*)&Vs[r * 68 + d] = pv[it];
        }
        __syncthreads();

        // prefetch next tile
        if (kt + 1 < 16) {
            const uint4* kb = kbase + (size_t)(s0 + 64) * (HD / 4);
            const uint4* vb = vbase + (size_t)(s0 + 64) * (HD / 4);
#pragma unroll
            for (int it = 0; it < 8; it++) {
                const int i = tid + 128 * it;
                pk[it] = kb[i];
                pv[it] = vb[i];
            }
        }

        // S = Q @ K^T  (warp's 16 rows x 64 cols)
        float s[8][4];
#pragma unroll
        for (int nt = 0; nt < 8; nt++)
#pragma unroll
            for (int f = 0; f < 4; f++) s[nt][f] = 0.0f;

#pragma unroll
        for (int ks = 0; ks < 8; ks++) {
            const int kk = ks * 8 + (lane & 3);
            unsigned a[4];
            const int mr = m0 + r0l;
            a[0] = Qs[mr * 68 + kk];
            a[1] = Qs[(mr + 8) * 68 + kk];
            a[2] = Qs[mr * 68 + kk + 4];
            a[3] = Qs[(mr + 8) * 68 + kk + 4];
#pragma unroll
            for (int nt = 0; nt < 8; nt++) {
                const int n = nt * 8 + r0l;
                unsigned b[2];
                b[0] = Ks[n * 68 + kk];
                b[1] = Ks[n * 68 + kk + 4];
                mma8(s[nt], a, b);
            }
        }

        // bias + online softmax (2 rows/lane; 4 lanes/row: xor 1,2)
#pragma unroll
        for (int rid = 0; rid < 2; rid++) {
            const int rloc = m0 + r0l + rid * 8;
            const int rg = tq0 + rloc;
            float vals[16];
            float mx = -1e30f;
#pragma unroll
            for (int nt = 0; nt < 8; nt++) {
#pragma unroll
                for (int cc = 0; cc < 2; cc++) {
                    const int sg = s0 + nt * 8 + 2 * (lane & 3) + cc;
                    int delta = min(max(sg - rg, -16), 16) + 16;
                    float v = s[nt][rid * 2 + cc] + qrs[rloc * NREL + delta];
                    vals[nt * 2 + cc] = v;
                    mx = fmaxf(mx, v);
                }
            }
            mx = fmaxf(mx, __shfl_xor_sync(0xffffffffu, mx, 1));
            mx = fmaxf(mx, __shfl_xor_sync(0xffffffffu, mx, 2));
            const float mnew = fmaxf(mrow[rid], mx);
            const float alpha = __expf(mrow[rid] - mnew);
            float rs = 0.0f;
#pragma unroll
            for (int j = 0; j < 16; j++) {
                vals[j] = __expf(vals[j] - mnew);
                rs += vals[j];
            }
            rs += __shfl_xor_sync(0xffffffffu, rs, 1);
            rs += __shfl_xor_sync(0xffffffffu, rs, 2);
            lrow[rid] = lrow[rid] * alpha + rs;
            mrow[rid] = mnew;
#pragma unroll
            for (int nt = 0; nt < 8; nt++) {
                o[nt][rid * 2]     *= alpha;
                o[nt][rid * 2 + 1] *= alpha;
            }
#pragma unroll
            for (int nt = 0; nt < 8; nt++) {
                const int c = nt * 8 + 2 * (lane & 3);
                uint2 pw = make_uint2(f2tf(vals[nt * 2]), f2tf(vals[nt * 2 + 1]));
                *(uint2*)&Ps[rloc * 68 + c] = pw;
            }
        }
        __syncwarp();   // P produced/consumed within this warp only

        // O += P @ V
#pragma unroll
        for (int ks = 0; ks < 8; ks++) {
            const int kk = ks * 8 + (lane & 3);
            unsigned a[4];
            const int mr = m0 + r0l;
            a[0] = Ps[mr * 68 + kk];
            a[1] = Ps[(mr + 8) * 68 + kk];
            a[2] = Ps[mr * 68 + kk + 4];
            a[3] = Ps[(mr + 8) * 68 + kk + 4];
#pragma unroll
            for (int nt = 0; nt < 8; nt++) {
                const int n = nt * 8 + r0l;
                unsigned b[2];
                b[0] = Vs[kk * 68 + n];
                b[1] = Vs[(kk + 4) * 68 + n];
                mma8(o[nt], a, b);
            }
        }
        __syncthreads();   // done reading Ks/Vs; safe to overwrite next iter
    }

    // write attn (tf32 bits) in [t][b][e] layout
    const int b = bh >> 4, h = bh & 15;
#pragma unroll
    for (int rid = 0; rid < 2; rid++) {
        const int t = tq0 + m0 + r0l + rid * 8;
        const float inv = 1.0f / lrow[rid];
#pragma unroll
        for (int nt = 0; nt < 8; nt++) {
            const int d = nt * 8 + 2 * (lane & 3);
            uint2 w = make_uint2(f2tf(o[nt][rid * 2] * inv),
                                 f2tf(o[nt][rid * 2 + 1] * inv));
            *(uint2*)&g_attn[(t * BATCH + b) * EMB + h * HD + d] = w;
        }
    }
}

// ---------------------------------------------------------------------------
extern "C" void kernel_launch(void* const* d_in, const int* in_sizes, int n_in,
                              void* d_out, int out_size)
{
    (void)in_sizes; (void)n_in; (void)out_size;
    const float* query = (const float*)d_in[0];   // [T,B,E]
    const float* w_in  = (const float*)d_in[1];   // [3E,E]
    const float* b_in  = (const float*)d_in[2];   // [3E]
    const float* relk  = (const float*)d_in[3];   // [33,E]
    const float* w_out = (const float*)d_in[4];   // [E,E]
    const float* b_out = (const float*)d_in[5];   // [E]
    float* out = (float*)d_out;                   // [T,B,E]

    float *qin, *win, *wout, *attn_ptr;
    cudaGetSymbolAddress((void**)&qin,  g_qin);
    cudaGetSymbolAddress((void**)&win,  g_win);
    cudaGetSymbolAddress((void**)&wout, g_wout);
    cudaGetSymbolAddress((void**)&attn_ptr, g_attn);

    // 0) one-time tf32 pre-conversion of fp32 operands
    cvt_tf32<<<4096, 256>>>(query, qin, 4096 * 1024 / 4);
    cvt_tf32<<<3072, 256>>>(w_in,  win, 3072 * 1024 / 4);
    cvt_tf32<<<1024, 256>>>(w_out, wout, 1024 * 1024 / 4);

    const size_t gemm_smem = (size_t)4 * GSTG * sizeof(unsigned);  // 73728 B
    cudaFuncSetAttribute(gemm_tc,
                         cudaFuncAttributeMaxDynamicSharedMemorySize,
                         (int)gemm_smem);

    // 1) fused QKV projection -> tf32 head-major q/k/v
    gemm_tc<<<dim3(24, 32), 256, gemm_smem>>>(
        qin, win, b_in, nullptr, 4096, 3072, 1024, 0);

    // 2) flash attention with relative bias
    const size_t attn_smem =
        (size_t)(4 * 64 * 68 + 33 * 68 + 64 * NREL) * sizeof(float);  // 87056 B
    cudaFuncSetAttribute(attn_tc,
                         cudaFuncAttributeMaxDynamicSharedMemorySize,
                         (int)attn_smem);
    attn_tc<<<dim3(16, 64), 128, attn_smem>>>(relk);

    // 3) output projection (writes fp32 final output)
    gemm_tc<<<dim3(8, 32), 256, gemm_smem>>>(
        attn_ptr, wout, b_out, out, 4096, 1024, 1024, 1);
}